// round 16
// baseline (speedup 1.0000x reference)
#include <cuda_runtime.h>
#include <cuda_fp16.h>
#include <math.h>
#include <stdint.h>

#define BATCH  4
#define HEIGHT 128
#define WIDTH  128
#define NPIX   (HEIGHT*WIDTH)      // 16384
#define M_TOT  (BATCH*NPIX)        // 65536
#define DIM    128
#define HEADS  8
#define DH     64
#define INNER  512
#define SLICE  64

// ---------------- scratch (device globals; no allocations) ----------------
__device__ __half g_xh [(size_t)M_TOT*DIM];    // fp16 input [pix][c]
__device__ __half g_wbh[18*INNER*DIM];         // [0,9): Wcomb (logits conv), [9,18): Wfx; [pt][o][ci]
__device__ float  g_bcomb[INNER];              // combined logits bias
__device__ __half g_fxmid[(size_t)M_TOT*INNER]; // conv_fx out (fp16)
__device__ __half g_sw   [(size_t)M_TOT*INNER]; // slice weights, layout [b n][h*64+g] (fp16)
__device__ float g_snorm[BATCH*HEADS*SLICE];
__device__ float g_stok [BATCH*HEADS*SLICE*DH];
__device__ float g_osl  [BATCH*HEADS*SLICE*DH];
__device__ __half g_pt  [BATCH*DIM*INNER];     // P^T: [b][o][h*64+g] (fp16)

// ---------------- helpers ----------------
__device__ __forceinline__ void cpa16(uint32_t dst, const void* src, int sz) {
    asm volatile("cp.async.cg.shared.global [%0], [%1], 16, %2;" :: "r"(dst), "l"(src), "r"(sz));
}
#define CP_COMMIT() asm volatile("cp.async.commit_group;" ::: "memory")
#define CP_WAIT2()  asm volatile("cp.async.wait_group 2;" ::: "memory")
#define CP_WAIT1()  asm volatile("cp.async.wait_group 1;" ::: "memory")
__device__ __forceinline__ uint32_t smem_u32(const void* p) {
    uint32_t a;
    asm("{ .reg .u64 t; cvta.to.shared.u64 t, %1; cvt.u32.u64 %0, t; }" : "=r"(a) : "l"(p));
    return a;
}
__device__ __forceinline__ void mma_f16_16x8x16(float* c, const uint32_t* a, const uint32_t* b) {
    asm volatile("mma.sync.aligned.m16n8k16.row.col.f32.f16.f16.f32 "
        "{%0,%1,%2,%3}, {%4,%5,%6,%7}, {%8,%9}, {%0,%1,%2,%3};"
        : "+f"(c[0]), "+f"(c[1]), "+f"(c[2]), "+f"(c[3])
        : "r"(a[0]), "r"(a[1]), "r"(a[2]), "r"(a[3]), "r"(b[0]), "r"(b[1]));
}
__device__ __forceinline__ void ldsm_x4(uint32_t* r, uint32_t addr) {
    asm volatile("ldmatrix.sync.aligned.m8n8.x4.shared.b16 {%0,%1,%2,%3}, [%4];"
        : "=r"(r[0]), "=r"(r[1]), "=r"(r[2]), "=r"(r[3]) : "r"(addr));
}
__device__ __forceinline__ void ldsm_x4_t(uint32_t* r, uint32_t addr) {
    asm volatile("ldmatrix.sync.aligned.m8n8.x4.trans.shared.b16 {%0,%1,%2,%3}, [%4];"
        : "=r"(r[0]), "=r"(r[1]), "=r"(r[2]), "=r"(r[3]) : "r"(addr));
}

// ---------------- prep: x->fp16, conv1 weights, zero accum ----------------
__global__ void prep_kernel(const float* __restrict__ x, const float* __restrict__ Wfx) {
    int stride = gridDim.x * blockDim.x;
    int tid = blockIdx.x * blockDim.x + threadIdx.x;
    for (size_t t = tid; t < (size_t)M_TOT*DIM; t += stride)
        g_xh[t] = __float2half(x[t]);
    for (int t = tid; t < 9*INNER*DIM; t += stride) {
        int ci = t & 127;
        int o  = (t >> 7) & 511;
        int p  = t >> 16;
        int ky = p / 3, kx = p % 3;
        g_wbh[9*INNER*DIM + t] = __float2half(Wfx[((o*DIM + ci)*3 + ky)*3 + kx]);
    }
    for (int t = tid; t < BATCH*HEADS*SLICE; t += stride)    g_snorm[t] = 0.f;
    for (int t = tid; t < BATCH*HEADS*SLICE*DH; t += stride) g_stok[t]  = 0.f;
}

// ---------------- wcomb: fold Ws into Wx -> logits conv weights + bcomb ----------------
__global__ __launch_bounds__(256) void wcomb_kernel(const float* __restrict__ Wx,
                                                    const float* __restrict__ Ws,
                                                    const float* __restrict__ bx,
                                                    const float* __restrict__ bs) {
    __shared__ float sWs[64][65];       // [g][c]
    __shared__ float sWx[64][144];      // [c][ci16*9+p]
    int h = blockIdx.x, cib = blockIdx.y;
    int tid = threadIdx.x;
    for (int e = tid; e < 64*64; e += 256)
        sWs[e >> 6][e & 63] = Ws[e];
    for (int e = tid; e < 64*144; e += 256) {
        int c = e / 144, r = e % 144;
        int ci = cib*16 + r/9, p = r % 9;
        sWx[c][r] = Wx[((h*64 + c)*DIM + ci)*9 + p];
    }
    __syncthreads();
    for (int e = tid; e < 64*144; e += 256) {
        int g = e / 144, r = e % 144;
        float s = 0.f;
        #pragma unroll 16
        for (int c = 0; c < 64; c++)
            s = fmaf(sWs[g][c], sWx[c][r], s);
        int ci = cib*16 + r/9, p = r % 9;
        g_wbh[((size_t)p*INNER + h*64 + g)*DIM + ci] = __float2half(s);
    }
    if (cib == 0 && tid < 64) {
        float s = bs[tid];
        for (int c = 0; c < 64; c++)
            s = fmaf(bx[h*64 + c], sWs[tid][c], s);
        g_bcomb[h*64 + tid] = s;
    }
}

// ---------------- fp16 mma conv; z=0: logits conv + fused softmax -> g_sw ----------------
#define ALDH 40
#define A_STAGEH (132*ALDH)
#define B_STAGEH (128*ALDH)
#define CONV_DSMEM ((2*A_STAGEH + 3*B_STAGEH)*2)   // 51840 B
#define NCHUNK 36

__device__ __forceinline__ void loadA_stage(int t, __half* sA, int tid, int b, int y) {
    int ky = t >> 2;
    int c0 = (t & 3) * 32;
    int yy = y + ky - 1;
    bool rowok = ((unsigned)yy < (unsigned)HEIGHT);
    int yys = rowok ? yy : 0;
    uint32_t sa = smem_u32(sA);
    const __half* rowbase = g_xh + ((size_t)(b*HEIGHT + yys)*WIDTH)*DIM + c0;
    #pragma unroll
    for (int r = 0; r < 3; r++) {
        int op = tid + r*256;
        if (op < 520) {
            int row = op >> 2, q = op & 3;
            int gx = row - 1;
            bool ok = rowok && ((unsigned)gx < (unsigned)WIDTH);
            const __half* src = rowbase + (size_t)(ok ? gx : 0)*DIM + q*8;
            cpa16(sa + (row*ALDH + q*8)*2, src, ok ? 16 : 0);
        }
    }
}

__device__ __forceinline__ void loadB_chunk(int j, __half* sB, int tid, int o0, const __half* wt) {
    int ky = j / 12, rem = j % 12;
    int c0 = (rem / 3) * 32;
    int kx = rem % 3;
    int p  = ky*3 + kx;
    uint32_t sb = smem_u32(sB);
    #pragma unroll
    for (int r = 0; r < 2; r++) {
        int op = tid + r*256;
        int row = op >> 2, q = op & 3;
        const __half* src = wt + ((size_t)(p*INNER + o0 + row))*DIM + c0 + q*8;
        cpa16(sb + (row*ALDH + q*8)*2, src, 16);
    }
}

__global__ __launch_bounds__(256, 2) void conv_mm_kernel(const float* __restrict__ bfx,
                                                         const float* __restrict__ temp_in) {
    extern __shared__ __half smh[];
    __half* sA = smh;
    __half* sB = smh + 2*A_STAGEH;

    int mt = blockIdx.x;
    int b  = mt >> 7, y = mt & 127;
    int m0 = mt * 128;
    int o0 = blockIdx.y * 128;
    int conv = blockIdx.z;
    const __half* wt = g_wbh + (size_t)conv*9*INNER*DIM;

    int tid  = threadIdx.x;
    int wid  = tid >> 5, lane = tid & 31;
    int g    = lane >> 2, tig = lane & 3;
    int wm   = wid >> 1, wn = wid & 1;

    int l15 = lane & 15;
    int ahalf = (lane >> 4) * 8;
    int b_i   = lane & 7;
    int b_grp = lane >> 3;
    int b_rowoff = (b_grp >> 1) * 8;
    int b_koff   = (b_grp & 1) * 8;

    float c[2][8][4];
    #pragma unroll
    for (int i = 0; i < 2; i++)
        #pragma unroll
        for (int j = 0; j < 8; j++)
            #pragma unroll
            for (int q = 0; q < 4; q++) c[i][j][q] = 0.f;

    loadA_stage(0, sA, tid, b, y);
    loadB_chunk(0, sB, tid, o0, wt);
    CP_COMMIT();
    loadB_chunk(1, sB + B_STAGEH, tid, o0, wt);
    CP_COMMIT();

    for (int it = 0; it < NCHUNK; ++it) {
        int jj = it + 2;
        if (jj < NCHUNK) {
            if (jj % 3 == 0) {
                int t = jj / 3;
                loadA_stage(t, sA + (t & 1)*A_STAGEH, tid, b, y);
            }
            loadB_chunk(jj, sB + (jj % 3)*B_STAGEH, tid, o0, wt);
        }
        CP_COMMIT();
        CP_WAIT2();
        __syncthreads();

        int kx = it % 3;
        int t  = it / 3;
        uint32_t saBase = smem_u32(sA + (t & 1)*A_STAGEH);
        uint32_t sbBase = smem_u32(sB + (it % 3)*B_STAGEH);
        #pragma unroll
        for (int ks = 0; ks < 2; ks++) {
            int k0 = ks*16;
            uint32_t a[2][4];
            #pragma unroll
            for (int mti = 0; mti < 2; mti++) {
                uint32_t addr = saBase
                    + ((wm*32 + mti*16 + l15 + kx)*ALDH + k0 + ahalf)*2;
                ldsm_x4(a[mti], addr);
            }
            uint32_t bf[8][2];
            #pragma unroll
            for (int bi = 0; bi < 4; bi++) {
                uint32_t t4[4];
                uint32_t addr = sbBase
                    + ((wn*64 + bi*16 + b_rowoff + b_i)*ALDH + k0 + b_koff)*2;
                ldsm_x4(t4, addr);
                bf[2*bi  ][0] = t4[0]; bf[2*bi  ][1] = t4[1];
                bf[2*bi+1][0] = t4[2]; bf[2*bi+1][1] = t4[3];
            }
            #pragma unroll
            for (int mti = 0; mti < 2; mti++)
                #pragma unroll
                for (int nti = 0; nti < 8; nti++)
                    mma_f16_16x8x16(c[mti][nti], a[mti], bf[nti]);
        }
        __syncthreads();
    }

    if (conv == 1) {
        // fx path: bias + fp16 store (unchanged)
        #pragma unroll
        for (int mti = 0; mti < 2; mti++) {
            int r0 = m0 + wm*32 + mti*16 + g;
            #pragma unroll
            for (int nti = 0; nti < 8; nti++) {
                int oc = o0 + wn*64 + nti*8 + tig*2;
                float b0 = bfx[oc], b1 = bfx[oc+1];
                __half2 v0 = __floats2half2_rn(c[mti][nti][0] + b0, c[mti][nti][1] + b1);
                __half2 v1 = __floats2half2_rn(c[mti][nti][2] + b0, c[mti][nti][3] + b1);
                *(__half2*)&g_fxmid[(size_t) r0   *INNER + oc] = v0;
                *(__half2*)&g_fxmid[(size_t)(r0+8)*INNER + oc] = v1;
            }
        }
    } else {
        // logits path: + bcomb, /temp, per-head softmax over 64 cols (quad = lanes 4g..4g+3)
        int h = blockIdx.y*2 + wn;
        float tt = temp_in[h];
        tt = fminf(fmaxf(tt, 0.1f), 5.0f);
        float invt = 1.f / tt;
        float part[16];
        #pragma unroll
        for (int q = 0; q < 16; q++) part[q] = 0.f;
        int nbase = (mt & 127)*128 + wm*32;
        #pragma unroll
        for (int mti = 0; mti < 2; mti++) {
            #pragma unroll
            for (int half = 0; half < 2; half++) {
                float v[16];
                #pragma unroll
                for (int nti = 0; nti < 8; nti++) {
                    int oc = o0 + wn*64 + nti*8 + tig*2;
                    v[nti*2]   = (c[mti][nti][half*2]   + g_bcomb[oc])   * invt;
                    v[nti*2+1] = (c[mti][nti][half*2+1] + g_bcomb[oc+1]) * invt;
                }
                float mx = v[0];
                #pragma unroll
                for (int q = 1; q < 16; q++) mx = fmaxf(mx, v[q]);
                mx = fmaxf(mx, __shfl_xor_sync(0xffffffffu, mx, 1));
                mx = fmaxf(mx, __shfl_xor_sync(0xffffffffu, mx, 2));
                float sm = 0.f;
                #pragma unroll
                for (int q = 0; q < 16; q++) { v[q] = __expf(v[q] - mx); sm += v[q]; }
                sm += __shfl_xor_sync(0xffffffffu, sm, 1);
                sm += __shfl_xor_sync(0xffffffffu, sm, 2);
                float inv = 1.f / sm;
                int nloc = nbase + mti*16 + g + half*8;
                __half* swp = g_sw + ((size_t)(b*NPIX + nloc))*INNER + o0 + wn*64;
                #pragma unroll
                for (int nti = 0; nti < 8; nti++) {
                    float e0 = v[nti*2] * inv, e1 = v[nti*2+1] * inv;
                    *(__half2*)&swp[nti*8 + tig*2] = __floats2half2_rn(e0, e1);
                    part[nti*2]   += e0;
                    part[nti*2+1] += e1;
                }
            }
        }
        // snorm: smem reduce then global atomics
        float* snloc = (float*)smh;       // stages dead after final sync
        if (tid < 128) snloc[tid] = 0.f;
        __syncthreads();
        #pragma unroll
        for (int nti = 0; nti < 8; nti++) {
            atomicAdd(&snloc[wn*64 + nti*8 + tig*2],     part[nti*2]);
            atomicAdd(&snloc[wn*64 + nti*8 + tig*2 + 1], part[nti*2+1]);
        }
        __syncthreads();
        if (tid < 128) {
            int hh = blockIdx.y*2 + (tid >> 6);
            atomicAdd(&g_snorm[(b*HEADS + hh)*SLICE + (tid & 63)], snloc[tid]);
        }
    }
}

// ---------------- slice_token: fp16 mma + trans ldmatrix + double-buffer (R15 proven) ----------------
#define SLD 72
__global__ __launch_bounds__(256) void stoken_mm_kernel() {
    __shared__ __align__(16) __half ssw[2][64*SLD];
    __shared__ __align__(16) __half sfx[2][64*SLD];
    int bh = blockIdx.y;
    int b  = bh >> 3, h = bh & 7;
    int n0 = blockIdx.x * 512;
    int tid = threadIdx.x;
    int wid = tid >> 5, lane = tid & 31;
    int g = lane >> 2, tig = lane & 3;
    int wm = wid >> 1, wn = wid & 1;

    int l8    = lane & 7;
    int khalf = (lane >> 4) * 8;
    int mhalf = ((lane >> 3) & 1) * 8;

    float c[4][4];
    #pragma unroll
    for (int i = 0; i < 4; i++)
        #pragma unroll
        for (int q = 0; q < 4; q++) c[i][q] = 0.f;

    auto load_stage = [&](int s, int nn) {
        const __half* swb = g_sw    + ((size_t)(b*NPIX + n0 + nn))*INNER + h*64;
        const __half* fxb = g_fxmid + ((size_t)(b*NPIX + n0 + nn))*INNER + h*DH;
        uint32_t sa = smem_u32(&ssw[s][0]), sb = smem_u32(&sfx[s][0]);
        #pragma unroll
        for (int r = 0; r < 2; r++) {
            int op = tid + r*256;
            int row = op >> 3, q = op & 7;
            cpa16(sa + (row*SLD + q*8)*2, swb + (size_t)row*INNER + q*8, 16);
            cpa16(sb + (row*SLD + q*8)*2, fxb + (size_t)row*INNER + q*8, 16);
        }
    };

    load_stage(0, 0);
    CP_COMMIT();

    for (int itr = 0; itr < 8; itr++) {
        if (itr + 1 < 8) load_stage((itr + 1) & 1, (itr + 1) * 64);
        CP_COMMIT();
        CP_WAIT1();
        __syncthreads();

        int s = itr & 1;
        uint32_t swBase = smem_u32(&ssw[s][0]);
        uint32_t fxBase = smem_u32(&sfx[s][0]);
        #pragma unroll
        for (int ks = 0; ks < 4; ks++) {
            int k0 = ks*16;
            uint32_t a4[4];
            ldsm_x4_t(a4, swBase + ((k0 + khalf + l8)*SLD + wm*16 + mhalf)*2);
            uint32_t bf[4][2];
            #pragma unroll
            for (int bi = 0; bi < 2; bi++) {
                uint32_t t4[4];
                ldsm_x4_t(t4, fxBase + ((k0 + khalf + l8)*SLD + wn*32 + bi*16 + mhalf)*2);
                bf[2*bi  ][0] = t4[0]; bf[2*bi+1][0] = t4[1];
                bf[2*bi  ][1] = t4[2]; bf[2*bi+1][1] = t4[3];
            }
            #pragma unroll
            for (int nti = 0; nti < 4; nti++)
                mma_f16_16x8x16(c[nti], a4, bf[nti]);
        }
        __syncthreads();
    }

    int r0 = wm*16 + g;
    #pragma unroll
    for (int nti = 0; nti < 4; nti++) {
        int col = wn*32 + nti*8 + tig*2;
        float* stp = g_stok + bh*4096;
        atomicAdd(&stp[ r0   *64 + col  ], c[nti][0]);
        atomicAdd(&stp[ r0   *64 + col+1], c[nti][1]);
        atomicAdd(&stp[(r0+8)*64 + col  ], c[nti][2]);
        atomicAdd(&stp[(r0+8)*64 + col+1], c[nti][3]);
    }
}

// ---------------- tiny M x M attention per (b,h) ----------------
#define AT_LD 68
#define ATTN_SMEM (5*64*AT_LD*4)
__global__ __launch_bounds__(256) void attn_kernel(const float* __restrict__ Wq,
                                                   const float* __restrict__ Wk,
                                                   const float* __restrict__ Wv) {
    extern __shared__ float smb[];
    float* tok = smb;
    float* wsm = smb + 1*64*AT_LD;
    float* qs  = smb + 2*64*AT_LD;
    float* ks_ = smb + 3*64*AT_LD;
    float* vs  = smb + 4*64*AT_LD;

    int bh  = blockIdx.x;
    int tid = threadIdx.x;

    for (int e = tid; e < 4096; e += 256) {
        int g = e >> 6, c = e & 63;
        float nm = g_snorm[bh*SLICE + g] + 1e-5f;
        tok[g*AT_LD + c] = g_stok[bh*4096 + e] / nm;
    }
    __syncthreads();

    #pragma unroll
    for (int w = 0; w < 3; w++) {
        const float* W = (w == 0) ? Wq : (w == 1) ? Wk : Wv;
        float* dst     = (w == 0) ? qs : (w == 1) ? ks_ : vs;
        for (int e = tid; e < 4096; e += 256)
            wsm[(e >> 6)*AT_LD + (e & 63)] = W[e];
        __syncthreads();
        for (int e = tid; e < 4096; e += 256) {
            int g = e >> 6, d = e & 63;
            float s = 0.f;
            #pragma unroll 8
            for (int c = 0; c < 64; c++)
                s = fmaf(tok[g*AT_LD + c], wsm[d*AT_LD + c], s);
            dst[g*AT_LD + d] = s;
        }
        __syncthreads();
    }
    for (int e = tid; e < 4096; e += 256) {
        int g = e >> 6, j = e & 63;
        float s = 0.f;
        #pragma unroll 8
        for (int d = 0; d < 64; d++)
            s = fmaf(qs[g*AT_LD + d], ks_[j*AT_LD + d], s);
        tok[g*AT_LD + j] = s * 0.125f;
    }
    __syncthreads();
    int wid = tid >> 5, lane = tid & 31;
    for (int r8 = 0; r8 < 8; r8++) {
        int row = wid*8 + r8;
        float v0 = tok[row*AT_LD + lane], v1 = tok[row*AT_LD + lane + 32];
        float mx = fmaxf(v0, v1);
        #pragma unroll
        for (int off = 16; off; off >>= 1)
            mx = fmaxf(mx, __shfl_xor_sync(0xffffffffu, mx, off));
        float e0 = __expf(v0 - mx), e1 = __expf(v1 - mx);
        float sm = e0 + e1;
        #pragma unroll
        for (int off = 16; off; off >>= 1)
            sm += __shfl_xor_sync(0xffffffffu, sm, off);
        float inv = 1.f / sm;
        tok[row*AT_LD + lane]      = e0 * inv;
        tok[row*AT_LD + lane + 32] = e1 * inv;
    }
    __syncthreads();
    for (int e = tid; e < 4096; e += 256) {
        int g = e >> 6, d = e & 63;
        float s = 0.f;
        #pragma unroll 8
        for (int j = 0; j < 64; j++)
            s = fmaf(tok[g*AT_LD + j], vs[j*AT_LD + d], s);
        g_osl[bh*4096 + e] = s;
    }
}

// ---------------- pproj: P^T (fp16 out) ----------------
__global__ __launch_bounds__(256) void pproj_kernel(const float* __restrict__ Wo) {
    __shared__ float sosl[64][65];
    __shared__ float swo [128][65];
    int bh = blockIdx.x;
    int b  = bh >> 3, h = bh & 7;
    int tid = threadIdx.x;

    for (int e = tid; e < 4096; e += 256) {
        int g = e >> 6, c = e & 63;
        sosl[g][c] = g_osl[bh*4096 + e];
    }
    for (int e = tid; e < 8192; e += 256) {
        int o = e >> 6, c = e & 63;
        swo[o][c] = Wo[o*INNER + h*DH + c];
    }
    __syncthreads();
    for (int e = tid; e < 8192; e += 256) {
        int o = e >> 6, g = e & 63;
        float s = 0.f;
        #pragma unroll 8
        for (int c = 0; c < 64; c++)
            s = fmaf(sosl[g][c], swo[o][c], s);
        g_pt[(b*DIM + o)*INNER + h*DH + g] = __float2half(s);
    }
}

// ---------------- out GEMM: fp16 mma, out_b = SW_b @ P_b^T ----------------
#define OGLDH 40
#define OG_STAGEH (128*OGLDH)
#define OG_DSMEM (6*OG_STAGEH*2)          // 61440 B
__global__ __launch_bounds__(256) void outgemm_kernel(const float* __restrict__ bo,
                                                      float* __restrict__ out) {
    extern __shared__ __half smhg[];
    __half* sA = smhg;
    __half* sB = smhg + 3*OG_STAGEH;

    int n0 = blockIdx.x * 128;
    int b  = blockIdx.y;
    int tid  = threadIdx.x;
    int wid  = tid >> 5, lane = tid & 31;
    int g    = lane >> 2, tig = lane & 3;
    int wm   = wid >> 1, wn = wid & 1;

    float c[2][8][4];
    #pragma unroll
    for (int i = 0; i < 2; i++)
        #pragma unroll
        for (int j = 0; j < 8; j++)
            #pragma unroll
            for (int q = 0; q < 4; q++) c[i][j][q] = 0.f;

    auto load_chunk = [&](int kk, __half* dA, __half* dB) {
        uint32_t sa = smem_u32(dA), sb = smem_u32(dB);
        #pragma unroll
        for (int r = 0; r < 2; r++) {
            int op = tid + r*256;
            int row = op >> 2, q = op & 3;
            const __half* srcA = g_sw + ((size_t)(b*NPIX) + n0 + row)*INNER + kk*32 + q*8;
            cpa16(sa + (row*OGLDH + q*8)*2, srcA, 16);
            const __half* srcB = g_pt + (size_t)(b*DIM + row)*INNER + kk*32 + q*8;
            cpa16(sb + (row*OGLDH + q*8)*2, srcB, 16);
        }
    };

    load_chunk(0, sA, sB); CP_COMMIT();
    load_chunk(1, sA + OG_STAGEH, sB + OG_STAGEH); CP_COMMIT();

    for (int it = 0; it < 16; ++it) {
        int j = it + 2;
        if (j < 16) {
            int s2 = j % 3;
            load_chunk(j, sA + s2*OG_STAGEH, sB + s2*OG_STAGEH);
        }
        CP_COMMIT();
        CP_WAIT2();
        __syncthreads();

        const __half* As = sA + (it % 3)*OG_STAGEH;
        const __half* Bs = sB + (it % 3)*OG_STAGEH;
        #pragma unroll
        for (int ks = 0; ks < 2; ks++) {
            int k0 = ks*16;
            uint32_t a[2][4];
            #pragma unroll
            for (int mti = 0; mti < 2; mti++) {
                int r = wm*32 + mti*16 + g;
                a[mti][0] = *(const uint32_t*)&As[ r     *OGLDH + k0 + 2*tig];
                a[mti][1] = *(const uint32_t*)&As[(r+8)  *OGLDH + k0 + 2*tig];
                a[mti][2] = *(const uint32_t*)&As[ r     *OGLDH + k0 + 2*tig + 8];
                a[mti][3] = *(const uint32_t*)&As[(r+8)  *OGLDH + k0 + 2*tig + 8];
            }
            uint32_t bf[8][2];
            #pragma unroll
            for (int nti = 0; nti < 8; nti++) {
                int n = wn*64 + nti*8 + g;
                bf[nti][0] = *(const uint32_t*)&Bs[n*OGLDH + k0 + 2*tig];
                bf[nti][1] = *(const uint32_t*)&Bs[n*OGLDH + k0 + 2*tig + 8];
            }
            #pragma unroll
            for (int mti = 0; mti < 2; mti++)
                #pragma unroll
                for (int nti = 0; nti < 8; nti++)
                    mma_f16_16x8x16(c[mti][nti], a[mti], bf[nti]);
        }
        __syncthreads();
    }

    #pragma unroll
    for (int mti = 0; mti < 2; mti++) {
        int r0 = b*NPIX + n0 + wm*32 + mti*16 + g;
        #pragma unroll
        for (int nti = 0; nti < 8; nti++) {
            int oc = wn*64 + nti*8 + tig*2;
            float b0 = bo[oc], b1 = bo[oc+1];
            float2 v0, v1;
            v0.x = c[mti][nti][0] + b0; v0.y = c[mti][nti][1] + b1;
            v1.x = c[mti][nti][2] + b0; v1.y = c[mti][nti][3] + b1;
            *(float2*)&out[(size_t) r0   *DIM + oc] = v0;
            *(float2*)&out[(size_t)(r0+8)*DIM + oc] = v1;
        }
    }
}

// ---------------- launch ----------------
extern "C" void kernel_launch(void* const* d_in, const int* in_sizes, int n_in,
                              void* d_out, int out_size) {
    const float* x           = (const float*)d_in[0];
    const float* temperature = (const float*)d_in[1];
    const float* Wx          = (const float*)d_in[2];
    const float* bx          = (const float*)d_in[3];
    const float* Wfx         = (const float*)d_in[4];
    const float* bfx         = (const float*)d_in[5];
    const float* Ws          = (const float*)d_in[6];
    const float* bs          = (const float*)d_in[7];
    const float* Wq          = (const float*)d_in[8];
    const float* Wk          = (const float*)d_in[9];
    const float* Wv          = (const float*)d_in[10];
    const float* Wo          = (const float*)d_in[11];
    const float* bo          = (const float*)d_in[12];
    float* out = (float*)d_out;

    cudaFuncSetAttribute(conv_mm_kernel, cudaFuncAttributeMaxDynamicSharedMemorySize, CONV_DSMEM);
    cudaFuncSetAttribute(attn_kernel, cudaFuncAttributeMaxDynamicSharedMemorySize, ATTN_SMEM);
    cudaFuncSetAttribute(outgemm_kernel, cudaFuncAttributeMaxDynamicSharedMemorySize, OG_DSMEM);

    prep_kernel<<<2048, 256>>>(x, Wfx);
    wcomb_kernel<<<dim3(HEADS, 8), 256>>>(Wx, Ws, bx, bs);
    conv_mm_kernel<<<dim3(M_TOT/128, 4, 2), 256, CONV_DSMEM>>>(bfx, temperature);
    stoken_mm_kernel<<<dim3(NPIX/512, BATCH*HEADS), 256>>>();
    attn_kernel<<<BATCH*HEADS, 256, ATTN_SMEM>>>(Wq, Wk, Wv);
    pproj_kernel<<<BATCH*HEADS, 256>>>(Wo);
    outgemm_kernel<<<dim3(NPIX/128, BATCH), 256, OG_DSMEM>>>(bo, out);
}

// round 17
// speedup vs baseline: 1.0213x; 1.0213x over previous
#include <cuda_runtime.h>
#include <cuda_fp16.h>
#include <math.h>
#include <stdint.h>

#define BATCH  4
#define HEIGHT 128
#define WIDTH  128
#define NPIX   (HEIGHT*WIDTH)      // 16384
#define M_TOT  (BATCH*NPIX)        // 65536
#define DIM    128
#define HEADS  8
#define DH     64
#define INNER  512
#define SLICE  64

// ---------------- scratch (device globals; no allocations) ----------------
__device__ __half g_xh [(size_t)M_TOT*DIM];    // fp16 input [pix][c]
__device__ __half g_wbh[18*INNER*DIM];         // conv weights per tap: [pt][o][ci], fp16
__device__ __half g_wsh[SLICE*DH];             // Ws fp16 [g][c]
__device__ __half g_xmid [(size_t)M_TOT*INNER]; // conv_x  out (fp16)
__device__ __half g_fxmid[(size_t)M_TOT*INNER]; // conv_fx out (fp16)
__device__ __half g_sw   [(size_t)BATCH*HEADS*NPIX*SLICE]; // slice weights (fp16)
__device__ float g_snorm[BATCH*HEADS*SLICE];
__device__ float g_stok [BATCH*HEADS*SLICE*DH];
__device__ float g_osl  [BATCH*HEADS*SLICE*DH];
__device__ __half g_pt  [BATCH*DIM*INNER];     // P^T: [b][o][h*64+g] (fp16)

// ---------------- helpers ----------------
__device__ __forceinline__ void cpa16(uint32_t dst, const void* src, int sz) {
    asm volatile("cp.async.cg.shared.global [%0], [%1], 16, %2;" :: "r"(dst), "l"(src), "r"(sz));
}
#define CP_COMMIT() asm volatile("cp.async.commit_group;" ::: "memory")
#define CP_WAIT2()  asm volatile("cp.async.wait_group 2;" ::: "memory")
#define CP_WAIT1()  asm volatile("cp.async.wait_group 1;" ::: "memory")
#define CP_WAIT0()  asm volatile("cp.async.wait_group 0;" ::: "memory")
__device__ __forceinline__ uint32_t smem_u32(const void* p) {
    uint32_t a;
    asm("{ .reg .u64 t; cvta.to.shared.u64 t, %1; cvt.u32.u64 %0, t; }" : "=r"(a) : "l"(p));
    return a;
}
__device__ __forceinline__ void mma_f16_16x8x16(float* c, const uint32_t* a, const uint32_t* b) {
    asm volatile("mma.sync.aligned.m16n8k16.row.col.f32.f16.f16.f32 "
        "{%0,%1,%2,%3}, {%4,%5,%6,%7}, {%8,%9}, {%0,%1,%2,%3};"
        : "+f"(c[0]), "+f"(c[1]), "+f"(c[2]), "+f"(c[3])
        : "r"(a[0]), "r"(a[1]), "r"(a[2]), "r"(a[3]), "r"(b[0]), "r"(b[1]));
}
__device__ __forceinline__ void ldsm_x4(uint32_t* r, uint32_t addr) {
    asm volatile("ldmatrix.sync.aligned.m8n8.x4.shared.b16 {%0,%1,%2,%3}, [%4];"
        : "=r"(r[0]), "=r"(r[1]), "=r"(r[2]), "=r"(r[3]) : "r"(addr));
}
__device__ __forceinline__ void ldsm_x4_t(uint32_t* r, uint32_t addr) {
    asm volatile("ldmatrix.sync.aligned.m8n8.x4.trans.shared.b16 {%0,%1,%2,%3}, [%4];"
        : "=r"(r[0]), "=r"(r[1]), "=r"(r[2]), "=r"(r[3]) : "r"(addr));
}

// ---------------- prep: vectorized x->fp16, Ws->fp16, zero accumulators ----------------
__global__ void prep_kernel(const float* __restrict__ x, const float* __restrict__ Ws) {
    int stride = gridDim.x * blockDim.x;
    int tid = blockIdx.x * blockDim.x + threadIdx.x;
    size_t nvec = (size_t)M_TOT*DIM/8;
    const float4* xv = (const float4*)x;
    uint4* ov = (uint4*)g_xh;
    for (size_t t = tid; t < nvec; t += stride) {
        float4 a = xv[2*t], b = xv[2*t+1];
        __half2 h0 = __floats2half2_rn(a.x, a.y);
        __half2 h1 = __floats2half2_rn(a.z, a.w);
        __half2 h2 = __floats2half2_rn(b.x, b.y);
        __half2 h3 = __floats2half2_rn(b.z, b.w);
        uint4 o;
        o.x = *(uint32_t*)&h0; o.y = *(uint32_t*)&h1;
        o.z = *(uint32_t*)&h2; o.w = *(uint32_t*)&h3;
        ov[t] = o;
    }
    for (int t = tid; t < SLICE*DH; t += stride)
        g_wsh[t] = __float2half(Ws[t]);
    for (int t = tid; t < BATCH*HEADS*SLICE; t += stride)    g_snorm[t] = 0.f;
    for (int t = tid; t < BATCH*HEADS*SLICE*DH; t += stride) g_stok[t]  = 0.f;
}

// ---------------- wtrans: coalesced smem-staged weight transpose ----------------
__global__ __launch_bounds__(256) void wtrans_kernel(const float* __restrict__ Wx,
                                                     const float* __restrict__ Wfx) {
    __shared__ float s[8*1152];
    int conv = blockIdx.y;
    int o0 = blockIdx.x * 8;
    int tid = threadIdx.x;
    const float* W = conv ? Wfx : Wx;
    for (int e = tid; e < 9216; e += 256)
        s[e] = W[(size_t)o0*1152 + e];
    __syncthreads();
    for (int e = tid; e < 9216; e += 256) {
        int ci = e & 127, o = (e >> 7) & 7, p = e >> 10;
        g_wbh[((size_t)(conv*9 + p)*INNER + o0 + o)*DIM + ci]
            = __float2half(s[o*1152 + ci*9 + p]);
    }
}

// ---------------- fp16 mma conv (round-13 proven) ----------------
#define ALDH 40
#define A_STAGEH (132*ALDH)
#define B_STAGEH (128*ALDH)
#define CONV_DSMEM ((2*A_STAGEH + 3*B_STAGEH)*2)   // 51840 B
#define NCHUNK 36

__device__ __forceinline__ void loadA_stage(int t, __half* sA, int tid, int b, int y) {
    int ky = t >> 2;
    int c0 = (t & 3) * 32;
    int yy = y + ky - 1;
    bool rowok = ((unsigned)yy < (unsigned)HEIGHT);
    int yys = rowok ? yy : 0;
    uint32_t sa = smem_u32(sA);
    const __half* rowbase = g_xh + ((size_t)(b*HEIGHT + yys)*WIDTH)*DIM + c0;
    #pragma unroll
    for (int r = 0; r < 3; r++) {
        int op = tid + r*256;
        if (op < 520) {
            int row = op >> 2, q = op & 3;
            int gx = row - 1;
            bool ok = rowok && ((unsigned)gx < (unsigned)WIDTH);
            const __half* src = rowbase + (size_t)(ok ? gx : 0)*DIM + q*8;
            cpa16(sa + (row*ALDH + q*8)*2, src, ok ? 16 : 0);
        }
    }
}

__device__ __forceinline__ void loadB_chunk(int j, __half* sB, int tid, int o0, const __half* wt) {
    int ky = j / 12, rem = j % 12;
    int c0 = (rem / 3) * 32;
    int kx = rem % 3;
    int p  = ky*3 + kx;
    uint32_t sb = smem_u32(sB);
    #pragma unroll
    for (int r = 0; r < 2; r++) {
        int op = tid + r*256;
        int row = op >> 2, q = op & 3;
        const __half* src = wt + ((size_t)(p*INNER + o0 + row))*DIM + c0 + q*8;
        cpa16(sb + (row*ALDH + q*8)*2, src, 16);
    }
}

__global__ __launch_bounds__(256, 2) void conv_mm_kernel(const float* __restrict__ bx,
                                                         const float* __restrict__ bfx) {
    extern __shared__ __half smh[];
    __half* sA = smh;
    __half* sB = smh + 2*A_STAGEH;

    int mt = blockIdx.x;
    int b  = mt >> 7, y = mt & 127;
    int m0 = mt * 128;
    int o0 = blockIdx.y * 128;
    int conv = blockIdx.z;
    const __half* wt = g_wbh + (size_t)conv*9*INNER*DIM;

    int tid  = threadIdx.x;
    int wid  = tid >> 5, lane = tid & 31;
    int g    = lane >> 2, tig = lane & 3;
    int wm   = wid >> 1, wn = wid & 1;

    int l15 = lane & 15;
    int ahalf = (lane >> 4) * 8;
    int b_i   = lane & 7;
    int b_grp = lane >> 3;
    int b_rowoff = (b_grp >> 1) * 8;
    int b_koff   = (b_grp & 1) * 8;

    float c[2][8][4];
    #pragma unroll
    for (int i = 0; i < 2; i++)
        #pragma unroll
        for (int j = 0; j < 8; j++)
            #pragma unroll
            for (int q = 0; q < 4; q++) c[i][j][q] = 0.f;

    loadA_stage(0, sA, tid, b, y);
    loadB_chunk(0, sB, tid, o0, wt);
    CP_COMMIT();
    loadB_chunk(1, sB + B_STAGEH, tid, o0, wt);
    CP_COMMIT();

    for (int it = 0; it < NCHUNK; ++it) {
        int jj = it + 2;
        if (jj < NCHUNK) {
            if (jj % 3 == 0) {
                int t = jj / 3;
                loadA_stage(t, sA + (t & 1)*A_STAGEH, tid, b, y);
            }
            loadB_chunk(jj, sB + (jj % 3)*B_STAGEH, tid, o0, wt);
        }
        CP_COMMIT();
        CP_WAIT2();
        __syncthreads();

        int kx = it % 3;
        int t  = it / 3;
        uint32_t saBase = smem_u32(sA + (t & 1)*A_STAGEH);
        uint32_t sbBase = smem_u32(sB + (it % 3)*B_STAGEH);
        #pragma unroll
        for (int ks = 0; ks < 2; ks++) {
            int k0 = ks*16;
            uint32_t a[2][4];
            #pragma unroll
            for (int mti = 0; mti < 2; mti++) {
                uint32_t addr = saBase
                    + ((wm*32 + mti*16 + l15 + kx)*ALDH + k0 + ahalf)*2;
                ldsm_x4(a[mti], addr);
            }
            uint32_t bf[8][2];
            #pragma unroll
            for (int bi = 0; bi < 4; bi++) {
                uint32_t t4[4];
                uint32_t addr = sbBase
                    + ((wn*64 + bi*16 + b_rowoff + b_i)*ALDH + k0 + b_koff)*2;
                ldsm_x4(t4, addr);
                bf[2*bi  ][0] = t4[0]; bf[2*bi  ][1] = t4[1];
                bf[2*bi+1][0] = t4[2]; bf[2*bi+1][1] = t4[3];
            }
            #pragma unroll
            for (int mti = 0; mti < 2; mti++)
                #pragma unroll
                for (int nti = 0; nti < 8; nti++)
                    mma_f16_16x8x16(c[mti][nti], a[mti], bf[nti]);
        }
        __syncthreads();
    }

    __half* outp = conv ? g_fxmid : g_xmid;
    const float* bias = conv ? bfx : bx;
    #pragma unroll
    for (int mti = 0; mti < 2; mti++) {
        int r0 = m0 + wm*32 + mti*16 + g;
        #pragma unroll
        for (int nti = 0; nti < 8; nti++) {
            int oc = o0 + wn*64 + nti*8 + tig*2;
            float b0 = bias[oc], b1 = bias[oc+1];
            __half2 v0 = __floats2half2_rn(c[mti][nti][0] + b0, c[mti][nti][1] + b1);
            __half2 v1 = __floats2half2_rn(c[mti][nti][2] + b0, c[mti][nti][3] + b1);
            *(__half2*)&outp[(size_t) r0   *INNER + oc] = v0;
            *(__half2*)&outp[(size_t)(r0+8)*INNER + oc] = v1;
        }
    }
}

// ---------------- logits: fp16 mma GEMM (64x64, K=64) + softmax (R15 proven) ----------------
#define LLD 72
__global__ __launch_bounds__(256) void logits_kernel(const float* __restrict__ bs,
                                                     const float* __restrict__ temp_in) {
    __shared__ __align__(16) __half xsh[64*LLD];
    __shared__ __align__(16) __half wsh[64*LLD];
    __shared__ __align__(16) float Ls[64][68];
    __shared__ float nrm[64];

    int bh = blockIdx.y;
    int b  = bh >> 3, h = bh & 7;
    int n0 = blockIdx.x * 64;
    int tid = threadIdx.x;
    int wid = tid >> 5, lane = tid & 31;
    int g_  = lane >> 2, tig = lane & 3;
    int wm2 = wid >> 1, wn2 = wid & 1;

    int l15 = lane & 15;
    int ahalf = (lane >> 4) * 8;
    int b_i   = lane & 7;
    int b_grp = lane >> 3;
    int b_rowoff = (b_grp >> 1) * 8;
    int b_koff   = (b_grp & 1) * 8;

    {
        uint32_t sx = smem_u32(xsh), sw_ = smem_u32(wsh);
        const __half* xbase = g_xmid + ((size_t)(b*NPIX + n0))*INNER + h*DH;
        #pragma unroll
        for (int r = 0; r < 2; r++) {
            int op = tid + r*256;
            int row = op >> 3, q = op & 7;
            cpa16(sx  + (row*LLD + q*8)*2, xbase + (size_t)row*INNER + q*8, 16);
            cpa16(sw_ + (row*LLD + q*8)*2, g_wsh + row*DH + q*8, 16);
        }
        CP_COMMIT();
    }
    if (tid < 64) nrm[tid] = 0.f;
    CP_WAIT0();
    __syncthreads();

    float cfr[4][4];
    #pragma unroll
    for (int i = 0; i < 4; i++)
        #pragma unroll
        for (int q = 0; q < 4; q++) cfr[i][q] = 0.f;

    uint32_t xBase = smem_u32(xsh), wBase = smem_u32(wsh);
    #pragma unroll
    for (int ks = 0; ks < 4; ks++) {
        int k0 = ks*16;
        uint32_t a4[4];
        ldsm_x4(a4, xBase + ((wm2*16 + l15)*LLD + k0 + ahalf)*2);
        uint32_t bf[4][2];
        #pragma unroll
        for (int bi = 0; bi < 2; bi++) {
            uint32_t t4[4];
            ldsm_x4(t4, wBase + ((wn2*32 + bi*16 + b_rowoff + b_i)*LLD + k0 + b_koff)*2);
            bf[2*bi  ][0] = t4[0]; bf[2*bi  ][1] = t4[1];
            bf[2*bi+1][0] = t4[2]; bf[2*bi+1][1] = t4[3];
        }
        #pragma unroll
        for (int nti = 0; nti < 4; nti++)
            mma_f16_16x8x16(cfr[nti], a4, bf[nti]);
    }
    float t = temp_in[h];
    t = fminf(fmaxf(t, 0.1f), 5.0f);
    float invt = 1.f / t;
    #pragma unroll
    for (int nti = 0; nti < 4; nti++) {
        int col = wn2*32 + nti*8 + tig*2;
        int r0 = wm2*16 + g_;
        Ls[r0    ][col  ] = (cfr[nti][0] + bs[col  ]) * invt;
        Ls[r0    ][col+1] = (cfr[nti][1] + bs[col+1]) * invt;
        Ls[r0 + 8][col  ] = (cfr[nti][2] + bs[col  ]) * invt;
        Ls[r0 + 8][col+1] = (cfr[nti][3] + bs[col+1]) * invt;
    }
    __syncthreads();

    float s0 = 0.f, s1 = 0.f;
    for (int r8 = 0; r8 < 8; r8++) {
        int row = wid*8 + r8;
        float v0 = Ls[row][lane], v1 = Ls[row][lane+32];
        float mx = fmaxf(v0, v1);
        #pragma unroll
        for (int off = 16; off; off >>= 1)
            mx = fmaxf(mx, __shfl_xor_sync(0xffffffffu, mx, off));
        float e0 = __expf(v0 - mx), e1 = __expf(v1 - mx);
        float sm = e0 + e1;
        #pragma unroll
        for (int off = 16; off; off >>= 1)
            sm += __shfl_xor_sync(0xffffffffu, sm, off);
        float inv = 1.f / sm;
        e0 *= inv; e1 *= inv;
        __half* swp = g_sw + ((size_t)bh*NPIX + n0 + row)*SLICE;
        swp[lane]      = __float2half(e0);
        swp[lane + 32] = __float2half(e1);
        s0 += e0; s1 += e1;
    }
    atomicAdd(&nrm[lane],      s0);
    atomicAdd(&nrm[lane + 32], s1);
    __syncthreads();
    if (tid < 64) atomicAdd(&g_snorm[bh*SLICE + tid], nrm[tid]);
}

// ---------------- slice_token: fp16 mma + trans ldmatrix + double-buffer (R15 proven) ----------------
#define SLD 72
__global__ __launch_bounds__(256) void stoken_mm_kernel() {
    __shared__ __align__(16) __half ssw[2][64*SLD];
    __shared__ __align__(16) __half sfx[2][64*SLD];
    int bh = blockIdx.y;
    int b  = bh >> 3, h = bh & 7;
    int n0 = blockIdx.x * 512;
    int tid = threadIdx.x;
    int wid = tid >> 5, lane = tid & 31;
    int g = lane >> 2, tig = lane & 3;
    int wm = wid >> 1, wn = wid & 1;

    int l8    = lane & 7;
    int khalf = (lane >> 4) * 8;
    int mhalf = ((lane >> 3) & 1) * 8;

    float c[4][4];
    #pragma unroll
    for (int i = 0; i < 4; i++)
        #pragma unroll
        for (int q = 0; q < 4; q++) c[i][q] = 0.f;

    auto load_stage = [&](int s, int nn) {
        const __half* swb = g_sw    + ((size_t)bh*NPIX + n0 + nn)*SLICE;
        const __half* fxb = g_fxmid + ((size_t)(b*NPIX + n0 + nn))*INNER + h*DH;
        uint32_t sa = smem_u32(&ssw[s][0]), sb = smem_u32(&sfx[s][0]);
        #pragma unroll
        for (int r = 0; r < 2; r++) {
            int op = tid + r*256;
            int row = op >> 3, q = op & 7;
            cpa16(sa + (row*SLD + q*8)*2, swb + (size_t)row*SLICE + q*8, 16);
            cpa16(sb + (row*SLD + q*8)*2, fxb + (size_t)row*INNER + q*8, 16);
        }
    };

    load_stage(0, 0);
    CP_COMMIT();

    for (int itr = 0; itr < 8; itr++) {
        if (itr + 1 < 8) load_stage((itr + 1) & 1, (itr + 1) * 64);
        CP_COMMIT();
        CP_WAIT1();
        __syncthreads();

        int s = itr & 1;
        uint32_t swBase = smem_u32(&ssw[s][0]);
        uint32_t fxBase = smem_u32(&sfx[s][0]);
        #pragma unroll
        for (int ks = 0; ks < 4; ks++) {
            int k0 = ks*16;
            uint32_t a4[4];
            ldsm_x4_t(a4, swBase + ((k0 + khalf + l8)*SLD + wm*16 + mhalf)*2);
            uint32_t bf[4][2];
            #pragma unroll
            for (int bi = 0; bi < 2; bi++) {
                uint32_t t4[4];
                ldsm_x4_t(t4, fxBase + ((k0 + khalf + l8)*SLD + wn*32 + bi*16 + mhalf)*2);
                bf[2*bi  ][0] = t4[0]; bf[2*bi+1][0] = t4[1];
                bf[2*bi  ][1] = t4[2]; bf[2*bi+1][1] = t4[3];
            }
            #pragma unroll
            for (int nti = 0; nti < 4; nti++)
                mma_f16_16x8x16(c[nti], a4, bf[nti]);
        }
        __syncthreads();
    }

    int r0 = wm*16 + g;
    #pragma unroll
    for (int nti = 0; nti < 4; nti++) {
        int col = wn*32 + nti*8 + tig*2;
        float* stp = g_stok + bh*4096;
        atomicAdd(&stp[ r0   *64 + col  ], c[nti][0]);
        atomicAdd(&stp[ r0   *64 + col+1], c[nti][1]);
        atomicAdd(&stp[(r0+8)*64 + col  ], c[nti][2]);
        atomicAdd(&stp[(r0+8)*64 + col+1], c[nti][3]);
    }
}

// ---------------- tiny M x M attention per (b,h) ----------------
#define AT_LD 68
#define ATTN_SMEM (5*64*AT_LD*4)
__global__ __launch_bounds__(256) void attn_kernel(const float* __restrict__ Wq,
                                                   const float* __restrict__ Wk,
                                                   const float* __restrict__ Wv) {
    extern __shared__ float smb[];
    float* tok = smb;
    float* wsm = smb + 1*64*AT_LD;
    float* qs  = smb + 2*64*AT_LD;
    float* ks_ = smb + 3*64*AT_LD;
    float* vs  = smb + 4*64*AT_LD;

    int bh  = blockIdx.x;
    int tid = threadIdx.x;

    for (int e = tid; e < 4096; e += 256) {
        int g = e >> 6, c = e & 63;
        float nm = g_snorm[bh*SLICE + g] + 1e-5f;
        tok[g*AT_LD + c] = g_stok[bh*4096 + e] / nm;
    }
    __syncthreads();

    #pragma unroll
    for (int w = 0; w < 3; w++) {
        const float* W = (w == 0) ? Wq : (w == 1) ? Wk : Wv;
        float* dst     = (w == 0) ? qs : (w == 1) ? ks_ : vs;
        for (int e = tid; e < 4096; e += 256)
            wsm[(e >> 6)*AT_LD + (e & 63)] = W[e];
        __syncthreads();
        for (int e = tid; e < 4096; e += 256) {
            int g = e >> 6, d = e & 63;
            float s = 0.f;
            #pragma unroll 8
            for (int c = 0; c < 64; c++)
                s = fmaf(tok[g*AT_LD + c], wsm[d*AT_LD + c], s);
            dst[g*AT_LD + d] = s;
        }
        __syncthreads();
    }
    for (int e = tid; e < 4096; e += 256) {
        int g = e >> 6, j = e & 63;
        float s = 0.f;
        #pragma unroll 8
        for (int d = 0; d < 64; d++)
            s = fmaf(qs[g*AT_LD + d], ks_[j*AT_LD + d], s);
        tok[g*AT_LD + j] = s * 0.125f;
    }
    __syncthreads();
    int wid = tid >> 5, lane = tid & 31;
    for (int r8 = 0; r8 < 8; r8++) {
        int row = wid*8 + r8;
        float v0 = tok[row*AT_LD + lane], v1 = tok[row*AT_LD + lane + 32];
        float mx = fmaxf(v0, v1);
        #pragma unroll
        for (int off = 16; off; off >>= 1)
            mx = fmaxf(mx, __shfl_xor_sync(0xffffffffu, mx, off));
        float e0 = __expf(v0 - mx), e1 = __expf(v1 - mx);
        float sm = e0 + e1;
        #pragma unroll
        for (int off = 16; off; off >>= 1)
            sm += __shfl_xor_sync(0xffffffffu, sm, off);
        float inv = 1.f / sm;
        tok[row*AT_LD + lane]      = e0 * inv;
        tok[row*AT_LD + lane + 32] = e1 * inv;
    }
    __syncthreads();
    for (int e = tid; e < 4096; e += 256) {
        int g = e >> 6, d = e & 63;
        float s = 0.f;
        #pragma unroll 8
        for (int j = 0; j < 64; j++)
            s = fmaf(tok[g*AT_LD + j], vs[j*AT_LD + d], s);
        g_osl[bh*4096 + e] = s;
    }
}

// ---------------- pproj: P^T (fp16 out) ----------------
__global__ __launch_bounds__(256) void pproj_kernel(const float* __restrict__ Wo) {
    __shared__ float sosl[64][65];
    __shared__ float swo [128][65];
    int bh = blockIdx.x;
    int b  = bh >> 3, h = bh & 7;
    int tid = threadIdx.x;

    for (int e = tid; e < 4096; e += 256) {
        int g = e >> 6, c = e & 63;
        sosl[g][c] = g_osl[bh*4096 + e];
    }
    for (int e = tid; e < 8192; e += 256) {
        int o = e >> 6, c = e & 63;
        swo[o][c] = Wo[o*INNER + h*DH + c];
    }
    __syncthreads();
    for (int e = tid; e < 8192; e += 256) {
        int o = e >> 6, g = e & 63;
        float s = 0.f;
        #pragma unroll 8
        for (int c = 0; c < 64; c++)
            s = fmaf(sosl[g][c], swo[o][c], s);
        g_pt[(b*DIM + o)*INNER + h*DH + g] = __float2half(s);
    }
}

// ---------------- out GEMM: fp16 mma, out_b = SW_b @ P_b^T (R14/15 proven) ----------------
#define OGLDH 40
#define OG_STAGEH (128*OGLDH)
#define OG_DSMEM (6*OG_STAGEH*2)          // 61440 B
__global__ __launch_bounds__(256) void outgemm_kernel(const float* __restrict__ bo,
                                                      float* __restrict__ out) {
    extern __shared__ __half smhg[];
    __half* sA = smhg;
    __half* sB = smhg + 3*OG_STAGEH;

    int n0 = blockIdx.x * 128;
    int b  = blockIdx.y;
    int tid  = threadIdx.x;
    int wid  = tid >> 5, lane = tid & 31;
    int g    = lane >> 2, tig = lane & 3;
    int wm   = wid >> 1, wn = wid & 1;

    float c[2][8][4];
    #pragma unroll
    for (int i = 0; i < 2; i++)
        #pragma unroll
        for (int j = 0; j < 8; j++)
            #pragma unroll
            for (int q = 0; q < 4; q++) c[i][j][q] = 0.f;

    auto load_chunk = [&](int kk, __half* dA, __half* dB) {
        int h  = kk >> 1;
        int g0 = (kk & 1) * 32;
        uint32_t sa = smem_u32(dA), sb = smem_u32(dB);
        #pragma unroll
        for (int r = 0; r < 2; r++) {
            int op = tid + r*256;
            int row = op >> 2, q = op & 3;
            const __half* srcA = g_sw + ((size_t)((b*HEADS + h)*NPIX) + n0 + row)*SLICE + g0 + q*8;
            cpa16(sa + (row*OGLDH + q*8)*2, srcA, 16);
            const __half* srcB = g_pt + (size_t)(b*DIM + row)*INNER + kk*32 + q*8;
            cpa16(sb + (row*OGLDH + q*8)*2, srcB, 16);
        }
    };

    load_chunk(0, sA, sB); CP_COMMIT();
    load_chunk(1, sA + OG_STAGEH, sB + OG_STAGEH); CP_COMMIT();

    for (int it = 0; it < 16; ++it) {
        int j = it + 2;
        if (j < 16) {
            int s2 = j % 3;
            load_chunk(j, sA + s2*OG_STAGEH, sB + s2*OG_STAGEH);
        }
        CP_COMMIT();
        CP_WAIT2();
        __syncthreads();

        const __half* As = sA + (it % 3)*OG_STAGEH;
        const __half* Bs = sB + (it % 3)*OG_STAGEH;
        #pragma unroll
        for (int ks = 0; ks < 2; ks++) {
            int k0 = ks*16;
            uint32_t a[2][4];
            #pragma unroll
            for (int mti = 0; mti < 2; mti++) {
                int r = wm*32 + mti*16 + g;
                a[mti][0] = *(const uint32_t*)&As[ r     *OGLDH + k0 + 2*tig];
                a[mti][1] = *(const uint32_t*)&As[(r+8)  *OGLDH + k0 + 2*tig];
                a[mti][2] = *(const uint32_t*)&As[ r     *OGLDH + k0 + 2*tig + 8];
                a[mti][3] = *(const uint32_t*)&As[(r+8)  *OGLDH + k0 + 2*tig + 8];
            }
            uint32_t bf[8][2];
            #pragma unroll
            for (int nti = 0; nti < 8; nti++) {
                int n = wn*64 + nti*8 + g;
                bf[nti][0] = *(const uint32_t*)&Bs[n*OGLDH + k0 + 2*tig];
                bf[nti][1] = *(const uint32_t*)&Bs[n*OGLDH + k0 + 2*tig + 8];
            }
            #pragma unroll
            for (int mti = 0; mti < 2; mti++)
                #pragma unroll
                for (int nti = 0; nti < 8; nti++)
                    mma_f16_16x8x16(c[mti][nti], a[mti], bf[nti]);
        }
        __syncthreads();
    }

    #pragma unroll
    for (int mti = 0; mti < 2; mti++) {
        int r0 = b*NPIX + n0 + wm*32 + mti*16 + g;
        #pragma unroll
        for (int nti = 0; nti < 8; nti++) {
            int oc = wn*64 + nti*8 + tig*2;
            float b0 = bo[oc], b1 = bo[oc+1];
            float2 v0, v1;
            v0.x = c[mti][nti][0] + b0; v0.y = c[mti][nti][1] + b1;
            v1.x = c[mti][nti][2] + b0; v1.y = c[mti][nti][3] + b1;
            *(float2*)&out[(size_t) r0   *DIM + oc] = v0;
            *(float2*)&out[(size_t)(r0+8)*DIM + oc] = v1;
        }
    }
}

// ---------------- launch ----------------
extern "C" void kernel_launch(void* const* d_in, const int* in_sizes, int n_in,
                              void* d_out, int out_size) {
    const float* x           = (const float*)d_in[0];
    const float* temperature = (const float*)d_in[1];
    const float* Wx          = (const float*)d_in[2];
    const float* bx          = (const float*)d_in[3];
    const float* Wfx         = (const float*)d_in[4];
    const float* bfx         = (const float*)d_in[5];
    const float* Ws          = (const float*)d_in[6];
    const float* bs          = (const float*)d_in[7];
    const float* Wq          = (const float*)d_in[8];
    const float* Wk          = (const float*)d_in[9];
    const float* Wv          = (const float*)d_in[10];
    const float* Wo          = (const float*)d_in[11];
    const float* bo          = (const float*)d_in[12];
    float* out = (float*)d_out;

    cudaFuncSetAttribute(conv_mm_kernel, cudaFuncAttributeMaxDynamicSharedMemorySize, CONV_DSMEM);
    cudaFuncSetAttribute(attn_kernel, cudaFuncAttributeMaxDynamicSharedMemorySize, ATTN_SMEM);
    cudaFuncSetAttribute(outgemm_kernel, cudaFuncAttributeMaxDynamicSharedMemorySize, OG_DSMEM);

    prep_kernel<<<2048, 256>>>(x, Ws);
    wtrans_kernel<<<dim3(64, 2), 256>>>(Wx, Wfx);
    conv_mm_kernel<<<dim3(M_TOT/128, 4, 2), 256, CONV_DSMEM>>>(bx, bfx);
    logits_kernel<<<dim3(NPIX/64, BATCH*HEADS), 256>>>(bs, temperature);
    stoken_mm_kernel<<<dim3(NPIX/512, BATCH*HEADS), 256>>>();
    attn_kernel<<<BATCH*HEADS, 256, ATTN_SMEM>>>(Wq, Wk, Wv);
    pproj_kernel<<<BATCH*HEADS, 256>>>(Wo);
    outgemm_kernel<<<dim3(NPIX/128, BATCH), 256, OG_DSMEM>>>(bo, out);
}